// round 8
// baseline (speedup 1.0000x reference)
#include <cuda_runtime.h>
#include <cuda_bf16.h>
#include <math.h>
#include <cstdint>

#define NB 256
#define NR 36
#define NL 40
#define ND 1024
#define MT (NB * NR)   /* 9216  */
#define NT (NB * NL)   /* 10240 */
#define EPSF 1e-8f
#define LAMS 9.0f

#define MROWS 9472     /* 9216 img rows + 256 pool_img */
#define NROWS 10496    /* 10240 cap rows + 256 pool_txt */

// ---- scratch (device globals; no allocation allowed) ----
__device__ float g_S[(size_t)MT * NT];           // S^T[n][m], leaky-relu'd (378MB)
__device__ __nv_bfloat16 g_Ah[(size_t)MROWS * ND];  // bf16 img_emb ++ pool_img
__device__ __nv_bfloat16 g_Bh[(size_t)NROWS * ND];  // bf16 cap_emb ++ pool_txt
__device__ float g_P[NB * NB * NR];
__device__ float g_Q[NB * NB * NL];
__device__ float g_G[NB * NR * NR];
__device__ float g_H[NB * NL * NL];
__device__ float g_base[NB * NB];
__device__ float g_w1i[NB];
__device__ float g_w1t[NB];

__device__ __forceinline__ float4 ldg4(const float* p) {
    return *reinterpret_cast<const float4*>(p);
}
__device__ __forceinline__ uint32_t pack_bf2(float x, float y) {
    __nv_bfloat162 h = __float22bfloat162_rn(make_float2(x, y));
    return *reinterpret_cast<uint32_t*>(&h);
}
__device__ __forceinline__ void mma_bf16(float* c, const uint32_t* a, const uint32_t* b) {
    asm volatile(
        "mma.sync.aligned.m16n8k16.row.col.f32.bf16.bf16.f32 "
        "{%0,%1,%2,%3}, {%4,%5,%6,%7}, {%8,%9}, {%0,%1,%2,%3};"
        : "+f"(c[0]), "+f"(c[1]), "+f"(c[2]), "+f"(c[3])
        : "r"(a[0]), "r"(a[1]), "r"(a[2]), "r"(a[3]), "r"(b[0]), "r"(b[1]));
}
__device__ __forceinline__ void cpa16(uint32_t saddr, const void* gaddr) {
    asm volatile("cp.async.ca.shared.global [%0], [%1], 16;"
                 :: "r"(saddr), "l"(gaddr) : "memory");
}

// ============================ bf16 conversion (augmented operands) ============================
__global__ void cvt_kernel(const float* __restrict__ img, const float* __restrict__ pimg,
                           const float* __restrict__ cap, const float* __restrict__ ptxt) {
    size_t g8 = (size_t)blockIdx.x * 256 + threadIdx.x;
    const size_t A8 = (size_t)MROWS * (ND / 8);
    const float* src;
    uint32_t* dst;
    if (g8 < A8) {
        size_t off = g8 * 8;
        size_t row = off >> 10, col = off & 1023;
        src = (row < 9216) ? (img + row * ND + col) : (pimg + (row - 9216) * ND + col);
        dst = reinterpret_cast<uint32_t*>(g_Ah) + g8 * 4;
    } else {
        size_t h8 = g8 - A8;
        size_t off = h8 * 8;
        size_t row = off >> 10, col = off & 1023;
        src = (row < 10240) ? (cap + row * ND + col) : (ptxt + (row - 10240) * ND + col);
        dst = reinterpret_cast<uint32_t*>(g_Bh) + h8 * 4;
    }
    float4 x = ldg4(src), y = ldg4(src + 4);
    *reinterpret_cast<uint4*>(dst) =
        make_uint4(pack_bf2(x.x, x.y), pack_bf2(x.z, x.w),
                   pack_bf2(y.x, y.y), pack_bf2(y.z, y.w));
}

// ============================ precompute kernels ============================
__global__ void norm_kernel(const float* __restrict__ pi, const float* __restrict__ pt) {
    int w = blockIdx.x * 8 + (threadIdx.x >> 5);
    int lane = threadIdx.x & 31;
    const float* src = (w < NB) ? (pi + (size_t)w * ND) : (pt + (size_t)(w - NB) * ND);
    float s = 0.f;
    for (int j = lane; j < ND; j += 32) { float v = src[j]; s = fmaf(v, v, s); }
#pragma unroll
    for (int o = 16; o; o >>= 1) s += __shfl_down_sync(0xffffffffu, s, o);
    if (lane == 0) {
        float r = sqrtf(s);
        if (w < NB) g_w1i[w] = r; else g_w1t[w - NB] = r;
    }
}

__global__ void sgemm_tn(const float* __restrict__ A, const float* __restrict__ Bm,
                         int M, int N, int K) {
    float* C = g_base;
    __shared__ float As[16 * 64];
    __shared__ float Bs[16 * 64];
    int tid = threadIdx.x;
    int tx = tid & 15, ty = tid >> 4;
    int m0 = blockIdx.y * 64, n0 = blockIdx.x * 64;
    int row = tid >> 2, q = tid & 3;
    float acc[4][4] = {};
    for (int k0 = 0; k0 < K; k0 += 16) {
        float4 a = ldg4(A + (size_t)(m0 + row) * K + k0 + q * 4);
        float4 bb = ldg4(Bm + (size_t)(n0 + row) * K + k0 + q * 4);
        As[(q * 4 + 0) * 64 + row] = a.x;  As[(q * 4 + 1) * 64 + row] = a.y;
        As[(q * 4 + 2) * 64 + row] = a.z;  As[(q * 4 + 3) * 64 + row] = a.w;
        Bs[(q * 4 + 0) * 64 + row] = bb.x; Bs[(q * 4 + 1) * 64 + row] = bb.y;
        Bs[(q * 4 + 2) * 64 + row] = bb.z; Bs[(q * 4 + 3) * 64 + row] = bb.w;
        __syncthreads();
#pragma unroll
        for (int k = 0; k < 16; k++) {
            float4 av = *(const float4*)(As + k * 64 + ty * 4);
            float4 bv = *(const float4*)(Bs + k * 64 + tx * 4);
            float aa[4] = {av.x, av.y, av.z, av.w};
            float bw[4] = {bv.x, bv.y, bv.z, bv.w};
#pragma unroll
            for (int ii = 0; ii < 4; ii++)
#pragma unroll
                for (int jj = 0; jj < 4; jj++)
                    acc[ii][jj] = fmaf(aa[ii], bw[jj], acc[ii][jj]);
        }
        __syncthreads();
    }
#pragma unroll
    for (int ii = 0; ii < 4; ii++)
#pragma unroll
        for (int jj = 0; jj < 4; jj++)
            C[(size_t)(m0 + ty * 4 + ii) * N + n0 + tx * 4 + jj] = acc[ii][jj];
}

// per-row Gram, 4x4 register-blocked, symmetric
__global__ void gram_kernel(const float* __restrict__ emb, int ROWS, int which) {
    extern __shared__ float Es[];
    float* out = which ? g_H : g_G;
    int b = blockIdx.x, tid = threadIdx.x;
    int wid = tid >> 5, lane = tid & 31;
    int n = ROWS * ND;
    int np = ROWS * ROWS;
    for (int idx = tid; idx < n; idx += 256) Es[idx] = emb[(size_t)b * n + idx];
    __syncthreads();
    int nt4 = ROWS / 4;
    int count = nt4 * (nt4 + 1) / 2;
    for (int p = wid; p < count; p += 8) {
        int pl = p, tr = 0;
        while (pl >= nt4 - tr) { pl -= nt4 - tr; tr++; }
        int tc = tr + pl;
        const float* E1 = Es + (size_t)tr * 4 * ND;
        const float* E2 = Es + (size_t)tc * 4 * ND;
        float acc[4][4] = {};
        for (int kk = 0; kk < ND; kk += 32) {
            int k = kk + lane;
            float e1[4], e2[4];
#pragma unroll
            for (int j = 0; j < 4; j++) { e1[j] = E1[j * ND + k]; e2[j] = E2[j * ND + k]; }
#pragma unroll
            for (int j = 0; j < 4; j++)
#pragma unroll
                for (int jj = 0; jj < 4; jj++)
                    acc[j][jj] = fmaf(e1[j], e2[jj], acc[j][jj]);
        }
#pragma unroll
        for (int j = 0; j < 4; j++)
#pragma unroll
            for (int jj = 0; jj < 4; jj++) {
#pragma unroll
                for (int o = 16; o; o >>= 1)
                    acc[j][jj] += __shfl_xor_sync(0xffffffffu, acc[j][jj], o);
            }
        if (lane == 0) {
#pragma unroll
            for (int j = 0; j < 4; j++)
#pragma unroll
                for (int jj = 0; jj < 4; jj++) {
                    float v = acc[j][jj];
                    out[(size_t)b * np + (tr * 4 + j) * ROWS + tc * 4 + jj] = v;
                    out[(size_t)b * np + (tc * 4 + jj) * ROWS + tr * 4 + j] = v;
                }
        }
    }
}

// ============================ bf16 cp.async pipelined GEMM ============================
#define BM 128
#define BN 256
#define BK 32
#define ASZW (BM * 20)
#define STGW (ASZW + BN * 20)
#define STAGES 4
#define GEMM_SMEM (STAGES * STGW * 4)

__global__ void __launch_bounds__(256, 1) s_gemm(const __nv_bfloat16* __restrict__ Ah,
                                                 const __nv_bfloat16* __restrict__ Bh,
                                                 float* __restrict__ S) {
    extern __shared__ uint32_t smw[];
    uint32_t sb;
    asm("{ .reg .u64 t; cvta.to.shared.u64 t, %1; cvt.u32.u64 %0, t; }" : "=r"(sb) : "l"(smw));
    const int tid = threadIdx.x;
    const int wid = tid >> 5;
    const int lane = tid & 31;
    const int g = lane >> 2;
    const int t = lane & 3;
    const int wm = wid >> 2;
    const int wn = wid & 3;
    const int by = blockIdx.y;
    const int bx = blockIdx.x;
    const int m0 = by * BM;
    const int n0 = bx * BN;
    const bool pBlk = (bx == 40);
    const bool qBlk = (by >= 72);

    const int arow = tid >> 2;
    const int ac = tid & 3;
    const __nv_bfloat16* Agp = (qBlk ? (Ah + (size_t)9216 * ND + (size_t)(by - 72) * BM * ND)
                                     : (Ah + (size_t)m0 * ND)) + (size_t)arow * ND + ac * 8;
    const __nv_bfloat16* Bgp = (pBlk ? (Bh + (size_t)10240 * ND)
                                     : (Bh + (size_t)n0 * ND)) + (size_t)arow * ND + ac * 8;
    const uint32_t sA = sb + (uint32_t)(arow * 20 + ac * 4) * 4;
    const uint32_t sB = sb + (uint32_t)(ASZW + arow * 20 + ac * 4) * 4;

    float cacc[4][8][4];
#pragma unroll
    for (int a = 0; a < 4; a++)
#pragma unroll
        for (int bb = 0; bb < 8; bb++)
#pragma unroll
            for (int cc = 0; cc < 4; cc++) cacc[a][bb][cc] = 0.f;

#define ISSUE(stg, kc) do {                                                    \
    uint32_t so = (uint32_t)(stg) * (STGW * 4);                                \
    _Pragma("unroll")                                                          \
    for (int j = 0; j < 2; j++)                                                \
        cpa16(sA + so + j * (64 * 20 * 4), Agp + (size_t)j * 64 * ND + (kc));  \
    _Pragma("unroll")                                                          \
    for (int j = 0; j < 4; j++)                                                \
        cpa16(sB + so + j * (64 * 20 * 4), Bgp + (size_t)j * 64 * ND + (kc));  \
} while (0)

#define COMPUTE(stg, ks) do {                                                  \
    const uint32_t* Aw = smw + (stg) * STGW;                                   \
    const uint32_t* Bw = Aw + ASZW;                                            \
    const int kw = (ks) * 8 + t;                                               \
    uint32_t af[4][4];                                                         \
    uint32_t bf[8][2];                                                         \
    _Pragma("unroll")                                                          \
    for (int mt = 0; mt < 4; mt++) {                                           \
        int r0 = (wm * 64 + mt * 16 + g) * 20;                                 \
        af[mt][0] = Aw[r0 + kw];                                               \
        af[mt][1] = Aw[r0 + 160 + kw];                                         \
        af[mt][2] = Aw[r0 + kw + 4];                                           \
        af[mt][3] = Aw[r0 + 160 + kw + 4];                                     \
    }                                                                          \
    _Pragma("unroll")                                                          \
    for (int nt = 0; nt < 8; nt++) {                                           \
        int c0 = (wn * 64 + nt * 8 + g) * 20;                                  \
        bf[nt][0] = Bw[c0 + kw];                                               \
        bf[nt][1] = Bw[c0 + kw + 4];                                           \
    }                                                                          \
    _Pragma("unroll")                                                          \
    for (int mt = 0; mt < 4; mt++)                                             \
        _Pragma("unroll")                                                      \
        for (int nt = 0; nt < 8; nt++)                                         \
            mma_bf16(cacc[mt][nt], af[mt], bf[nt]);                            \
} while (0)

    ISSUE(0, 0);  asm volatile("cp.async.commit_group;" ::: "memory");
    ISSUE(1, 32); asm volatile("cp.async.commit_group;" ::: "memory");
    ISSUE(2, 64); asm volatile("cp.async.commit_group;" ::: "memory");

#pragma unroll 1
    for (int c = 0; c < 32; c++) {
        asm volatile("cp.async.wait_group 2;" ::: "memory");
        __syncthreads();
        COMPUTE(c & 3, 0);
        COMPUTE(c & 3, 1);
        if (c < 29) ISSUE((c + 3) & 3, (c + 3) * BK);
        asm volatile("cp.async.commit_group;" ::: "memory");
    }

    if (pBlk && qBlk) return;

    if (!pBlk && !qBlk) {
#pragma unroll
        for (int mt = 0; mt < 4; mt++) {
            int m = m0 + wm * 64 + mt * 16 + g;
#pragma unroll
            for (int nt = 0; nt < 8; nt++) {
                int n = n0 + wn * 64 + nt * 8 + 2 * t;
                float v0 = cacc[mt][nt][0]; v0 = (v0 >= 0.f) ? v0 : 0.1f * v0;
                float v1 = cacc[mt][nt][1]; v1 = (v1 >= 0.f) ? v1 : 0.1f * v1;
                float v2 = cacc[mt][nt][2]; v2 = (v2 >= 0.f) ? v2 : 0.1f * v2;
                float v3 = cacc[mt][nt][3]; v3 = (v3 >= 0.f) ? v3 : 0.1f * v3;
                __stcs(S + (size_t)n * MT + m, v0);
                __stcs(S + (size_t)(n + 1) * MT + m, v1);
                __stcs(S + (size_t)n * MT + m + 8, v2);
                __stcs(S + (size_t)(n + 1) * MT + m + 8, v3);
            }
        }
    } else if (pBlk) {
#pragma unroll
        for (int mt = 0; mt < 4; mt++) {
            int m = m0 + wm * 64 + mt * 16 + g;
#pragma unroll
            for (int nt = 0; nt < 8; nt++) {
                int i = wn * 64 + nt * 8 + 2 * t;
                __stcs(g_P + (size_t)i * MT + m, cacc[mt][nt][0]);
                __stcs(g_P + (size_t)(i + 1) * MT + m, cacc[mt][nt][1]);
                __stcs(g_P + (size_t)i * MT + m + 8, cacc[mt][nt][2]);
                __stcs(g_P + (size_t)(i + 1) * MT + m + 8, cacc[mt][nt][3]);
            }
        }
    } else {
#pragma unroll
        for (int mt = 0; mt < 4; mt++) {
            int b = (by - 72) * BM + wm * 64 + mt * 16 + g;
#pragma unroll
            for (int nt = 0; nt < 8; nt++) {
                int n = n0 + wn * 64 + nt * 8 + 2 * t;
                __stcs(g_Q + (size_t)b * NT + n, cacc[mt][nt][0]);
                __stcs(g_Q + (size_t)b * NT + n + 1, cacc[mt][nt][1]);
                __stcs(g_Q + (size_t)(b + 8) * NT + n, cacc[mt][nt][2]);
                __stcs(g_Q + (size_t)(b + 8) * NT + n + 1, cacc[mt][nt][3]);
            }
        }
    }
#undef ISSUE
#undef COMPUTE
}

// ============================ per-pair epilogue: symmetric quadratic form ============================
// smem words: FS 0 (1600, [r][l] stride 41) | A2 1600 ([r][l] stride 44, 1584)
//   C2 3200 ([l][r] stride 44, 1760) | Gs 4960 (1296) | Hs 6260 (1600)
//   w2p1 7860 ([l]*47+tile, 1880) | w2p2 9740 ([r]*57+tile, 2052)
#define EPI_WORDS 11792
#define EPI_SMEM (EPI_WORDS * 4)

__global__ void __launch_bounds__(128) pair_epilogue(const float* __restrict__ S,
                                                     float* __restrict__ out) {
    extern __shared__ float sh[];
    __shared__ float Pb[NR], Qi[NL], rnl[NR], cnl[NL], s1s[NL], s2s[NR];
    __shared__ float w12a[NL], w12b[NR];
    __shared__ int dec1[45], dec2[55];
    float* FS = sh;
    float* A2 = sh + 1600;
    float* C2 = sh + 3200;
    float* Gs = sh + 4960;
    float* Hs = sh + 6260;
    float* w2p1 = sh + 7860;
    float* w2p2 = sh + 9740;
    const int i = blockIdx.x, b = blockIdx.y, tid = threadIdx.x;

    const float* Sp = S + (size_t)i * NL * MT + (size_t)b * NR;
    for (int idx = tid; idx < NR * NL; idx += 128) {
        int l = idx / NR, r = idx - l * NR;
        FS[r * 41 + l] = __ldcs(Sp + (size_t)l * MT + r);
    }
    for (int idx = tid; idx < NR * NR; idx += 128) Gs[idx] = g_G[(size_t)b * (NR * NR) + idx];
    for (int idx = tid; idx < NL * NL; idx += 128) Hs[idx] = g_H[(size_t)i * (NL * NL) + idx];
    if (tid < NR) Pb[tid] = g_P[(size_t)i * MT + b * NR + tid];
    else if (tid >= 64 && tid < 64 + NL) Qi[tid - 64] = g_Q[(size_t)b * NT + i * NL + (tid - 64)];
    if (tid < 45) {                 // decode upper-tri (n=9)
        int rem = tid, rg = 0;
        while (rem >= 9 - rg) { rem -= 9 - rg; rg++; }
        dec1[tid] = (rg << 8) | (rg + rem);
    }
    if (tid >= 64 && tid < 64 + 55) {   // decode upper-tri (n=10)
        int rem = tid - 64, lg = 0;
        while (rem >= 10 - lg) { rem -= 10 - lg; lg++; }
        dec2[tid - 64] = (lg << 8) | (lg + rem);
    }
    __syncthreads();

    if (tid < NL) {                         // column norms over r -> lambda/cn
        int l = tid; float s = 0.f;
#pragma unroll
        for (int r = 0; r < NR; r++) { float v = FS[r * 41 + l]; s = fmaf(v, v, s); }
        cnl[l] = LAMS / (sqrtf(s) + EPSF);
    } else if (tid >= 64 && tid < 64 + NR) { // row norms over l -> lambda/rn
        int r = tid - 64; float s = 0.f;
#pragma unroll
        for (int l = 0; l < NL; l++) { float v = FS[r * 41 + l]; s = fmaf(v, v, s); }
        rnl[r] = LAMS / (sqrtf(s) + EPSF);
    }
    __syncthreads();

    // exp matrices: A2[r][l] (t2i weights), C2[l][r] (i2t weights)
    for (int idx = tid; idx < NR * NL; idx += 128) {
        int l = idx / NR, r = idx - l * NR;
        float v = FS[r * 41 + l];
        A2[r * 44 + l] = __expf(v * rnl[r]);
        C2[l * 44 + r] = __expf(v * cnl[l]);
    }
    __syncthreads();

    // symmetric quadratic-form items: 450 t2i + 495 i2t
    for (int e = tid; e < 945; e += 128) {
        if (e < 450) {
            int task = e / 10, lq = e - task * 10;
            int d = dec1[task];
            int rg = d >> 8, rg2 = d & 255;
            float sc = (rg == rg2) ? 1.f : 2.f;
            const float* Gb = Gs + (rg * 4) * 36 + rg2 * 4;
            float4 g0 = *(const float4*)(Gb);
            float4 g1 = *(const float4*)(Gb + 36);
            float4 g2 = *(const float4*)(Gb + 72);
            float4 g3 = *(const float4*)(Gb + 108);
            const float* Au = A2 + (rg * 4) * 44 + lq * 4;
            const float* Av = A2 + (rg2 * 4) * 44 + lq * 4;
            float4 u0 = *(const float4*)(Au);
            float4 u1 = *(const float4*)(Au + 44);
            float4 u2 = *(const float4*)(Au + 88);
            float4 u3 = *(const float4*)(Au + 132);
            float4 v0 = *(const float4*)(Av);
            float4 v1 = *(const float4*)(Av + 44);
            float4 v2 = *(const float4*)(Av + 88);
            float4 v3 = *(const float4*)(Av + 132);
            float4 s;
            // t_k = sum_j G[j][k] * u_j ; s = sum_k t_k * v_k   (vector over 4 l's)
            float4 t0, t1, t2, t3;
#define VMAD(D, A, SCL, C) D.x = fmaf(A.x, SCL, C.x); D.y = fmaf(A.y, SCL, C.y); \
                           D.z = fmaf(A.z, SCL, C.z); D.w = fmaf(A.w, SCL, C.w);
#define VMUL(D, A, SCL) D.x = A.x * SCL; D.y = A.y * SCL; D.z = A.z * SCL; D.w = A.w * SCL;
            VMUL(t0, u0, g0.x) VMAD(t0, u1, g1.x, t0) VMAD(t0, u2, g2.x, t0) VMAD(t0, u3, g3.x, t0)
            VMUL(t1, u0, g0.y) VMAD(t1, u1, g1.y, t1) VMAD(t1, u2, g2.y, t1) VMAD(t1, u3, g3.y, t1)
            VMUL(t2, u0, g0.z) VMAD(t2, u1, g1.z, t2) VMAD(t2, u2, g2.z, t2) VMAD(t2, u3, g3.z, t2)
            VMUL(t3, u0, g0.w) VMAD(t3, u1, g1.w, t3) VMAD(t3, u2, g2.w, t3) VMAD(t3, u3, g3.w, t3)
            s.x = t0.x * v0.x; s.y = t0.y * v0.y; s.z = t0.z * v0.z; s.w = t0.w * v0.w;
            VMAD(s, t1, 1.f, s)   // placeholder no-op? replaced below
            // correct: s += t1*v1 etc (elementwise products)
            s.x = fmaf(t1.x, v1.x, s.x - t1.x); // (never executed path guard)
            ;
            // -- rewritten cleanly below --
            s.x = t0.x * v0.x + t1.x * v1.x + t2.x * v2.x + t3.x * v3.x;
            s.y = t0.y * v0.y + t1.y * v1.y + t2.y * v2.y + t3.y * v3.y;
            s.z = t0.z * v0.z + t1.z * v1.z + t2.z * v2.z + t3.z * v3.z;
            s.w = t0.w * v0.w + t1.w * v1.w + t2.w * v2.w + t3.w * v3.w;
            int l = lq * 4;
            w2p1[(l + 0) * 47 + task] = s.x * sc;
            w2p1[(l + 1) * 47 + task] = s.y * sc;
            w2p1[(l + 2) * 47 + task] = s.z * sc;
            w2p1[(l + 3) * 47 + task] = s.w * sc;
        } else {
            int e2 = e - 450;
            int task = e2 / 9, rq = e2 - task * 9;
            int d = dec2[task];
            int lg = d >> 8, lg2 = d & 255;
            float sc = (lg == lg2) ? 1.f : 2.f;
            const float* Hb = Hs + (lg * 4) * 40 + lg2 * 4;
            float4 g0 = *(const float4*)(Hb);
            float4 g1 = *(const float4*)(Hb + 40);
            float4 g2 = *(const float4*)(Hb + 80);
            float4 g3 = *(const float4*)(Hb + 120);
            const float* Cu = C2 + (lg * 4) * 44 + rq * 4;
            const float* Cv = C2 + (lg2 * 4) * 44 + rq * 4;
            float4 u0 = *(const float4*)(Cu);
            float4 u1 = *(const float4*)(Cu + 44);
            float4 u2 = *(const float4*)(Cu + 88);
            float4 u3 = *(const float4*)(Cu + 132);
            float4 v0 = *(const float4*)(Cv);
            float4 v1 = *(const float4*)(Cv + 44);
            float4 v2 = *(const float4*)(Cv + 88);
            float4 v3 = *(const float4*)(Cv + 132);
            float4 t0, t1, t2, t3, s;
            VMUL(t0, u0, g0.x) VMAD(t0, u1, g1.x, t0) VMAD(t0, u2, g2.x, t0) VMAD(t0, u3, g3.x, t0)
            VMUL(t1, u0, g0.y) VMAD(t1, u1, g1.y, t1) VMAD(t1, u2, g2.y, t1) VMAD(t1, u3, g3.y, t1)
            VMUL(t2, u0, g0.z) VMAD(t2, u1, g1.z, t2) VMAD(t2, u2, g2.z, t2) VMAD(t2, u3, g3.z, t2)
            VMUL(t3, u0, g0.w) VMAD(t3, u1, g1.w, t3) VMAD(t3, u2, g2.w, t3) VMAD(t3, u3, g3.w, t3)
            s.x = t0.x * v0.x + t1.x * v1.x + t2.x * v2.x + t3.x * v3.x;
            s.y = t0.y * v0.y + t1.y * v1.y + t2.y * v2.y + t3.y * v3.y;
            s.z = t0.z * v0.z + t1.z * v1.z + t2.z * v2.z + t3.z * v3.z;
            s.w = t0.w * v0.w + t1.w * v1.w + t2.w * v2.w + t3.w * v3.w;
            int r = rq * 4;
            w2p2[(r + 0) * 57 + task] = s.x * sc;
            w2p2[(r + 1) * 57 + task] = s.y * sc;
            w2p2[(r + 2) * 57 + task] = s.z * sc;
            w2p2[(r + 3) * 57 + task] = s.w * sc;
#undef VMAD
#undef VMUL
        }
    }

    // w12 tasks (19): t2i per l-quad (10), i2t per r-quad (9)
    for (int task = tid; task < 19; task += 128) {
        if (task < 10) {
            int lq = task;
            float4 s = make_float4(0.f, 0.f, 0.f, 0.f);
#pragma unroll
            for (int r = 0; r < NR; r++) {
                float p = Pb[r];
                float4 a = *(const float4*)(A2 + r * 44 + lq * 4);
                s.x = fmaf(a.x, p, s.x); s.y = fmaf(a.y, p, s.y);
                s.z = fmaf(a.z, p, s.z); s.w = fmaf(a.w, p, s.w);
            }
            w12a[lq * 4 + 0] = s.x; w12a[lq * 4 + 1] = s.y;
            w12a[lq * 4 + 2] = s.z; w12a[lq * 4 + 3] = s.w;
        } else {
            int rq = task - 10;
            float4 s = make_float4(0.f, 0.f, 0.f, 0.f);
#pragma unroll
            for (int l = 0; l < NL; l++) {
                float q = Qi[l];
                float4 c = *(const float4*)(C2 + l * 44 + rq * 4);
                s.x = fmaf(c.x, q, s.x); s.y = fmaf(c.y, q, s.y);
                s.z = fmaf(c.z, q, s.z); s.w = fmaf(c.w, q, s.w);
            }
            w12b[rq * 4 + 0] = s.x; w12b[rq * 4 + 1] = s.y;
            w12b[rq * 4 + 2] = s.z; w12b[rq * 4 + 3] = s.w;
        }
    }
    __syncthreads();

    if (tid < NL) {                          // t2i: word l
        int l = tid; float w2 = 0.f;
#pragma unroll
        for (int t = 0; t < 45; t++) w2 += w2p1[l * 47 + t];
        float den = fmaxf(g_w1t[i] * sqrtf(fmaxf(w2, 0.f)), EPSF);
        s1s[l] = __fdividef(w12a[l], den);
    } else if (tid >= 64 && tid < 64 + NR) { // i2t: region r
        int r = tid - 64; float w2 = 0.f;
#pragma unroll
        for (int t = 0; t < 55; t++) w2 += w2p2[r * 57 + t];
        float den = fmaxf(g_w1i[b] * sqrtf(fmaxf(w2, 0.f)), EPSF);
        s2s[r] = __fdividef(w12b[r], den);
    }
    __syncthreads();

    if (tid == 0) {
        float m1 = 0.f, m2 = 0.f;
#pragma unroll
        for (int l = 0; l < NL; l++) m1 += s1s[l];
#pragma unroll
        for (int r = 0; r < NR; r++) m2 += s2s[r];
        out[(size_t)b * NB + i] = g_base[b * NB + i] + m1 * (1.f / NL) + m2 * (1.f / NR);
    }
}

// ============================ launch ============================
extern "C" void kernel_launch(void* const* d_in, const int* in_sizes, int n_in,
                              void* d_out, int out_size) {
    (void)in_sizes; (void)n_in; (void)out_size;
    const float* pool_img = (const float*)d_in[0];
    const float* img_emb  = (const float*)d_in[1];
    const float* pool_txt = (const float*)d_in[2];
    const float* cap_emb  = (const float*)d_in[3];
    float* out = (float*)d_out;

    cudaFuncSetAttribute((const void*)gram_kernel,
                         cudaFuncAttributeMaxDynamicSharedMemorySize, NL * ND * 4);
    cudaFuncSetAttribute((const void*)s_gemm,
                         cudaFuncAttributeMaxDynamicSharedMemorySize, GEMM_SMEM);
    cudaFuncSetAttribute((const void*)pair_epilogue,
                         cudaFuncAttributeMaxDynamicSharedMemorySize, EPI_SMEM);

    float* dS = nullptr;
    cudaGetSymbolAddress((void**)&dS, g_S);
    __nv_bfloat16* dAh = nullptr; cudaGetSymbolAddress((void**)&dAh, g_Ah);
    __nv_bfloat16* dBh = nullptr; cudaGetSymbolAddress((void**)&dBh, g_Bh);

    // order: s_gemm stays at launch index 3 (profiled slot)
    cvt_kernel<<<9984, 256>>>(img_emb, pool_img, cap_emb, pool_txt);
    gram_kernel<<<NB, 256, NR * ND * 4>>>(img_emb, NR, 0);
    gram_kernel<<<NB, 256, NL * ND * 4>>>(cap_emb, NL, 1);
    s_gemm<<<dim3(41, 74), 256, GEMM_SMEM>>>(dAh, dBh, dS);
    norm_kernel<<<64, 256>>>(pool_img, pool_txt);
    sgemm_tn<<<dim3(NB / 64, NB / 64), 256>>>(pool_img, pool_txt, NB, NB, ND);
    pair_epilogue<<<dim3(NB, NB), 128, EPI_SMEM>>>(dS, out);
}

// round 9
// speedup vs baseline: 1.3597x; 1.3597x over previous
#include <cuda_runtime.h>
#include <cuda_bf16.h>
#include <math.h>
#include <cstdint>

#define NB 256
#define NR 36
#define NL 40
#define ND 1024
#define MT (NB * NR)   /* 9216  */
#define NT (NB * NL)   /* 10240 */
#define EPSF 1e-8f
#define LAMS 9.0f

#define MROWS 9472     /* 9216 img rows + 256 pool_img */
#define NROWS 10496    /* 10240 cap rows + 256 pool_txt */

// ---- scratch (device globals; no allocation allowed) ----
__device__ float g_S[(size_t)MT * NT];           // S^T[n][m], leaky-relu'd (378MB)
__device__ __nv_bfloat16 g_Ah[(size_t)MROWS * ND];  // bf16 img_emb ++ pool_img
__device__ __nv_bfloat16 g_Bh[(size_t)NROWS * ND];  // bf16 cap_emb ++ pool_txt
__device__ float g_P[NB * NB * NR];
__device__ float g_Q[NB * NB * NL];
__device__ float g_G[NB * NR * NR];
__device__ float g_H[NB * NL * NL];
__device__ float g_base[NB * NB];
__device__ float g_w1i[NB];
__device__ float g_w1t[NB];

__device__ __forceinline__ float4 ldg4(const float* p) {
    return *reinterpret_cast<const float4*>(p);
}
__device__ __forceinline__ uint32_t pack_bf2(float x, float y) {
    __nv_bfloat162 h = __float22bfloat162_rn(make_float2(x, y));
    return *reinterpret_cast<uint32_t*>(&h);
}
__device__ __forceinline__ void mma_bf16(float* c, const uint32_t* a, const uint32_t* b) {
    asm volatile(
        "mma.sync.aligned.m16n8k16.row.col.f32.bf16.bf16.f32 "
        "{%0,%1,%2,%3}, {%4,%5,%6,%7}, {%8,%9}, {%0,%1,%2,%3};"
        : "+f"(c[0]), "+f"(c[1]), "+f"(c[2]), "+f"(c[3])
        : "r"(a[0]), "r"(a[1]), "r"(a[2]), "r"(a[3]), "r"(b[0]), "r"(b[1]));
}
__device__ __forceinline__ void cpa16(uint32_t saddr, const void* gaddr) {
    asm volatile("cp.async.ca.shared.global [%0], [%1], 16;"
                 :: "r"(saddr), "l"(gaddr) : "memory");
}
__device__ __forceinline__ void ldsm_x4(uint32_t& r0, uint32_t& r1, uint32_t& r2,
                                        uint32_t& r3, uint32_t addr) {
    asm volatile("ldmatrix.sync.aligned.m8n8.x4.shared.b16 {%0,%1,%2,%3}, [%4];"
                 : "=r"(r0), "=r"(r1), "=r"(r2), "=r"(r3) : "r"(addr));
}

// ============================ bf16 conversion (augmented operands) ============================
__global__ void cvt_kernel(const float* __restrict__ img, const float* __restrict__ pimg,
                           const float* __restrict__ cap, const float* __restrict__ ptxt) {
    size_t g8 = (size_t)blockIdx.x * 256 + threadIdx.x;
    const size_t A8 = (size_t)MROWS * (ND / 8);
    const float* src;
    uint32_t* dst;
    if (g8 < A8) {
        size_t off = g8 * 8;
        size_t row = off >> 10, col = off & 1023;
        src = (row < 9216) ? (img + row * ND + col) : (pimg + (row - 9216) * ND + col);
        dst = reinterpret_cast<uint32_t*>(g_Ah) + g8 * 4;
    } else {
        size_t h8 = g8 - A8;
        size_t off = h8 * 8;
        size_t row = off >> 10, col = off & 1023;
        src = (row < 10240) ? (cap + row * ND + col) : (ptxt + (row - 10240) * ND + col);
        dst = reinterpret_cast<uint32_t*>(g_Bh) + h8 * 4;
    }
    float4 x = ldg4(src), y = ldg4(src + 4);
    *reinterpret_cast<uint4*>(dst) =
        make_uint4(pack_bf2(x.x, x.y), pack_bf2(x.z, x.w),
                   pack_bf2(y.x, y.y), pack_bf2(y.z, y.w));
}

// ============================ precompute kernels ============================
__global__ void norm_kernel(const float* __restrict__ pi, const float* __restrict__ pt) {
    int w = blockIdx.x * 8 + (threadIdx.x >> 5);
    int lane = threadIdx.x & 31;
    const float* src = (w < NB) ? (pi + (size_t)w * ND) : (pt + (size_t)(w - NB) * ND);
    float s = 0.f;
    for (int j = lane; j < ND; j += 32) { float v = src[j]; s = fmaf(v, v, s); }
#pragma unroll
    for (int o = 16; o; o >>= 1) s += __shfl_down_sync(0xffffffffu, s, o);
    if (lane == 0) {
        float r = sqrtf(s);
        if (w < NB) g_w1i[w] = r; else g_w1t[w - NB] = r;
    }
}

__global__ void sgemm_tn(const float* __restrict__ A, const float* __restrict__ Bm,
                         int M, int N, int K) {
    float* C = g_base;
    __shared__ float As[16 * 64];
    __shared__ float Bs[16 * 64];
    int tid = threadIdx.x;
    int tx = tid & 15, ty = tid >> 4;
    int m0 = blockIdx.y * 64, n0 = blockIdx.x * 64;
    int row = tid >> 2, q = tid & 3;
    float acc[4][4] = {};
    for (int k0 = 0; k0 < K; k0 += 16) {
        float4 a = ldg4(A + (size_t)(m0 + row) * K + k0 + q * 4);
        float4 bb = ldg4(Bm + (size_t)(n0 + row) * K + k0 + q * 4);
        As[(q * 4 + 0) * 64 + row] = a.x;  As[(q * 4 + 1) * 64 + row] = a.y;
        As[(q * 4 + 2) * 64 + row] = a.z;  As[(q * 4 + 3) * 64 + row] = a.w;
        Bs[(q * 4 + 0) * 64 + row] = bb.x; Bs[(q * 4 + 1) * 64 + row] = bb.y;
        Bs[(q * 4 + 2) * 64 + row] = bb.z; Bs[(q * 4 + 3) * 64 + row] = bb.w;
        __syncthreads();
#pragma unroll
        for (int k = 0; k < 16; k++) {
            float4 av = *(const float4*)(As + k * 64 + ty * 4);
            float4 bv = *(const float4*)(Bs + k * 64 + tx * 4);
            float aa[4] = {av.x, av.y, av.z, av.w};
            float bw[4] = {bv.x, bv.y, bv.z, bv.w};
#pragma unroll
            for (int ii = 0; ii < 4; ii++)
#pragma unroll
                for (int jj = 0; jj < 4; jj++)
                    acc[ii][jj] = fmaf(aa[ii], bw[jj], acc[ii][jj]);
        }
        __syncthreads();
    }
#pragma unroll
    for (int ii = 0; ii < 4; ii++)
#pragma unroll
        for (int jj = 0; jj < 4; jj++)
            C[(size_t)(m0 + ty * 4 + ii) * N + n0 + tx * 4 + jj] = acc[ii][jj];
}

// per-row Gram, 4x4 register-blocked, symmetric
__global__ void gram_kernel(const float* __restrict__ emb, int ROWS, int which) {
    extern __shared__ float Es[];
    float* out = which ? g_H : g_G;
    int b = blockIdx.x, tid = threadIdx.x;
    int wid = tid >> 5, lane = tid & 31;
    int n = ROWS * ND;
    int np = ROWS * ROWS;
    for (int idx = tid; idx < n; idx += 256) Es[idx] = emb[(size_t)b * n + idx];
    __syncthreads();
    int nt4 = ROWS / 4;
    int count = nt4 * (nt4 + 1) / 2;
    for (int p = wid; p < count; p += 8) {
        int pl = p, tr = 0;
        while (pl >= nt4 - tr) { pl -= nt4 - tr; tr++; }
        int tc = tr + pl;
        const float* E1 = Es + (size_t)tr * 4 * ND;
        const float* E2 = Es + (size_t)tc * 4 * ND;
        float acc[4][4] = {};
        for (int kk = 0; kk < ND; kk += 32) {
            int k = kk + lane;
            float e1[4], e2[4];
#pragma unroll
            for (int j = 0; j < 4; j++) { e1[j] = E1[j * ND + k]; e2[j] = E2[j * ND + k]; }
#pragma unroll
            for (int j = 0; j < 4; j++)
#pragma unroll
                for (int jj = 0; jj < 4; jj++)
                    acc[j][jj] = fmaf(e1[j], e2[jj], acc[j][jj]);
        }
#pragma unroll
        for (int j = 0; j < 4; j++)
#pragma unroll
            for (int jj = 0; jj < 4; jj++) {
#pragma unroll
                for (int o = 16; o; o >>= 1)
                    acc[j][jj] += __shfl_xor_sync(0xffffffffu, acc[j][jj], o);
            }
        if (lane == 0) {
#pragma unroll
            for (int j = 0; j < 4; j++)
#pragma unroll
                for (int jj = 0; jj < 4; jj++) {
                    float v = acc[j][jj];
                    out[(size_t)b * np + (tr * 4 + j) * ROWS + tc * 4 + jj] = v;
                    out[(size_t)b * np + (tc * 4 + jj) * ROWS + tr * 4 + j] = v;
                }
        }
    }
}

// ============================ bf16 cp.async pipelined GEMM (LDSM fragments) ============================
#define BM 128
#define BN 256
#define BK 32
#define ASZW (BM * 20)
#define STGW (ASZW + BN * 20)
#define STAGES 4
#define GEMM_SMEM (STAGES * STGW * 4)

__global__ void __launch_bounds__(256, 1) s_gemm(const __nv_bfloat16* __restrict__ Ah,
                                                 const __nv_bfloat16* __restrict__ Bh,
                                                 float* __restrict__ S) {
    extern __shared__ uint32_t smw[];
    uint32_t sb;
    asm("{ .reg .u64 t; cvta.to.shared.u64 t, %1; cvt.u32.u64 %0, t; }" : "=r"(sb) : "l"(smw));
    const int tid = threadIdx.x;
    const int wid = tid >> 5;
    const int lane = tid & 31;
    const int g = lane >> 2;
    const int t = lane & 3;
    const int wm = wid >> 2;
    const int wn = wid & 3;
    const int by = blockIdx.y;
    const int bx = blockIdx.x;
    const int m0 = by * BM;
    const int n0 = bx * BN;
    const bool pBlk = (bx == 40);
    const bool qBlk = (by >= 72);

    const int arow = tid >> 2;
    const int ac = tid & 3;
    const __nv_bfloat16* Agp = (qBlk ? (Ah + (size_t)9216 * ND + (size_t)(by - 72) * BM * ND)
                                     : (Ah + (size_t)m0 * ND)) + (size_t)arow * ND + ac * 8;
    const __nv_bfloat16* Bgp = (pBlk ? (Bh + (size_t)10240 * ND)
                                     : (Bh + (size_t)n0 * ND)) + (size_t)arow * ND + ac * 8;
    const uint32_t sA = sb + (uint32_t)(arow * 20 + ac * 4) * 4;
    const uint32_t sB = sb + (uint32_t)(ASZW + arow * 20 + ac * 4) * 4;

    // ldmatrix lane geometry
    const int alr = (lane & 7) + ((lane >> 3) & 1) * 8;   // A row within 16-tile
    const int ahf = (lane >> 4) & 1;                      // A k-half
    const int blr = (lane & 7) + ((lane >> 4) & 1) * 8;   // B row within 16-tile
    const int bhf = (lane >> 3) & 1;                      // B k-half
    const uint32_t aFrag = sb + (uint32_t)(((wm * 64 + alr) * 20) + ahf * 4) * 4;
    const uint32_t bFrag = sb + (uint32_t)((ASZW + (wn * 64 + blr) * 20) + bhf * 4) * 4;

    float cacc[4][8][4];
#pragma unroll
    for (int a = 0; a < 4; a++)
#pragma unroll
        for (int bb = 0; bb < 8; bb++)
#pragma unroll
            for (int cc = 0; cc < 4; cc++) cacc[a][bb][cc] = 0.f;

#define ISSUE(stg, kc) do {                                                    \
    uint32_t so = (uint32_t)(stg) * (STGW * 4);                                \
    _Pragma("unroll")                                                          \
    for (int j = 0; j < 2; j++)                                                \
        cpa16(sA + so + j * (64 * 20 * 4), Agp + (size_t)j * 64 * ND + (kc));  \
    _Pragma("unroll")                                                          \
    for (int j = 0; j < 4; j++)                                                \
        cpa16(sB + so + j * (64 * 20 * 4), Bgp + (size_t)j * 64 * ND + (kc));  \
} while (0)

#define COMPUTE(stg, ks) do {                                                  \
    const uint32_t so = (uint32_t)(stg) * (STGW * 4) + (ks) * 32;              \
    uint32_t af[4][4];                                                         \
    uint32_t bf[8][2];                                                         \
    _Pragma("unroll")                                                          \
    for (int mt = 0; mt < 4; mt++)                                             \
        ldsm_x4(af[mt][0], af[mt][1], af[mt][2], af[mt][3],                    \
                aFrag + so + mt * (16 * 20 * 4));                              \
    _Pragma("unroll")                                                          \
    for (int np = 0; np < 4; np++)                                             \
        ldsm_x4(bf[2 * np][0], bf[2 * np][1], bf[2 * np + 1][0],               \
                bf[2 * np + 1][1], bFrag + so + np * (16 * 20 * 4));           \
    _Pragma("unroll")                                                          \
    for (int mt = 0; mt < 4; mt++)                                             \
        _Pragma("unroll")                                                      \
        for (int nt = 0; nt < 8; nt++)                                         \
            mma_bf16(cacc[mt][nt], af[mt], bf[nt]);                            \
} while (0)

    ISSUE(0, 0);  asm volatile("cp.async.commit_group;" ::: "memory");
    ISSUE(1, 32); asm volatile("cp.async.commit_group;" ::: "memory");
    ISSUE(2, 64); asm volatile("cp.async.commit_group;" ::: "memory");

#pragma unroll 1
    for (int c = 0; c < 32; c++) {
        asm volatile("cp.async.wait_group 2;" ::: "memory");
        __syncthreads();
        COMPUTE(c & 3, 0);
        COMPUTE(c & 3, 1);
        if (c < 29) ISSUE((c + 3) & 3, (c + 3) * BK);
        asm volatile("cp.async.commit_group;" ::: "memory");
    }

    if (pBlk && qBlk) return;

    if (!pBlk && !qBlk) {
#pragma unroll
        for (int mt = 0; mt < 4; mt++) {
            int m = m0 + wm * 64 + mt * 16 + g;
#pragma unroll
            for (int nt = 0; nt < 8; nt++) {
                int n = n0 + wn * 64 + nt * 8 + 2 * t;
                float v0 = cacc[mt][nt][0]; v0 = (v0 >= 0.f) ? v0 : 0.1f * v0;
                float v1 = cacc[mt][nt][1]; v1 = (v1 >= 0.f) ? v1 : 0.1f * v1;
                float v2 = cacc[mt][nt][2]; v2 = (v2 >= 0.f) ? v2 : 0.1f * v2;
                float v3 = cacc[mt][nt][3]; v3 = (v3 >= 0.f) ? v3 : 0.1f * v3;
                __stcs(S + (size_t)n * MT + m, v0);
                __stcs(S + (size_t)(n + 1) * MT + m, v1);
                __stcs(S + (size_t)n * MT + m + 8, v2);
                __stcs(S + (size_t)(n + 1) * MT + m + 8, v3);
            }
        }
    } else if (pBlk) {
#pragma unroll
        for (int mt = 0; mt < 4; mt++) {
            int m = m0 + wm * 64 + mt * 16 + g;
#pragma unroll
            for (int nt = 0; nt < 8; nt++) {
                int i = wn * 64 + nt * 8 + 2 * t;
                __stcs(g_P + (size_t)i * MT + m, cacc[mt][nt][0]);
                __stcs(g_P + (size_t)(i + 1) * MT + m, cacc[mt][nt][1]);
                __stcs(g_P + (size_t)i * MT + m + 8, cacc[mt][nt][2]);
                __stcs(g_P + (size_t)(i + 1) * MT + m + 8, cacc[mt][nt][3]);
            }
        }
    } else {
#pragma unroll
        for (int mt = 0; mt < 4; mt++) {
            int b = (by - 72) * BM + wm * 64 + mt * 16 + g;
#pragma unroll
            for (int nt = 0; nt < 8; nt++) {
                int n = n0 + wn * 64 + nt * 8 + 2 * t;
                __stcs(g_Q + (size_t)b * NT + n, cacc[mt][nt][0]);
                __stcs(g_Q + (size_t)b * NT + n + 1, cacc[mt][nt][1]);
                __stcs(g_Q + (size_t)(b + 8) * NT + n, cacc[mt][nt][2]);
                __stcs(g_Q + (size_t)(b + 8) * NT + n + 1, cacc[mt][nt][3]);
            }
        }
    }
#undef ISSUE
#undef COMPUTE
}

// ============================ per-pair epilogue (Round-7 proven version) ============================
// word offsets: FS 0 (1600, stride 41) | Am 1600 (40x44) | Cm 3360 (36x44)
//               Hs 4944 (40x40) | Gs 6544 (36x36) | w2p1 7840 (40x9) | w2p2 8200 (36x10)
#define EPI_WORDS 8560
#define EPI_SMEM (EPI_WORDS * 4)

__global__ void __launch_bounds__(128) pair_epilogue(const float* __restrict__ S,
                                                     float* __restrict__ out) {
    extern __shared__ float sh[];
    __shared__ float Pb[NR], Qi[NL], rnl[NR], cnl[NL], s1s[NL], s2s[NR];
    float* FS = sh;
    float* Am = sh + 1600;
    float* Cm = sh + 3360;
    float* Hs = sh + 4944;
    float* Gs = sh + 6544;
    float* w2p1 = sh + 7840;
    float* w2p2 = sh + 8200;
    const int i = blockIdx.x, b = blockIdx.y, tid = threadIdx.x;

    const float* Sp = S + (size_t)i * NL * MT + (size_t)b * NR;
    for (int idx = tid; idx < NR * NL; idx += 128) {
        int l = idx / NR, r = idx - l * NR;
        FS[r * 41 + l] = __ldcs(Sp + (size_t)l * MT + r);
    }
    for (int idx = tid; idx < NR * NR; idx += 128) Gs[idx] = g_G[(size_t)b * (NR * NR) + idx];
    for (int idx = tid; idx < NL * NL; idx += 128) Hs[idx] = g_H[(size_t)i * (NL * NL) + idx];
    if (tid < NR) Pb[tid] = g_P[(size_t)i * MT + b * NR + tid];
    else if (tid >= 64 && tid < 64 + NL) Qi[tid - 64] = g_Q[(size_t)b * NT + i * NL + (tid - 64)];
    __syncthreads();

    if (tid < NL) {                         // column norms over r -> lambda/cn
        int l = tid; float s = 0.f;
#pragma unroll
        for (int r = 0; r < NR; r++) { float v = FS[r * 41 + l]; s = fmaf(v, v, s); }
        cnl[l] = LAMS / (sqrtf(s) + EPSF);
    } else if (tid >= 64 && tid < 64 + NR) { // row norms over l -> lambda/rn
        int r = tid - 64; float s = 0.f;
#pragma unroll
        for (int l = 0; l < NL; l++) { float v = FS[r * 41 + l]; s = fmaf(v, v, s); }
        rnl[r] = LAMS / (sqrtf(s) + EPSF);
    }
    __syncthreads();

    for (int idx = tid; idx < NR * NL; idx += 128) {
        int l = idx / NR, r = idx - l * NR;
        float v = FS[r * 41 + l];
        Am[l * 44 + r] = __expf(v * rnl[r]);
        Cm[r * 44 + l] = __expf(v * cnl[l]);
    }
    __syncthreads();

    // fused mini-GEMM + quadratic form: 180 tasks, each a 4x4 tile
    for (int task = tid; task < 180; task += 128) {
        float4 acc0 = make_float4(0.f, 0.f, 0.f, 0.f);
        float4 acc1 = acc0, acc2 = acc0, acc3 = acc0;
        float4 st0 = acc0, st1 = acc0, st2 = acc0, st3 = acc0;
        if (task < 90) {
            int lg = task / 9, rg = task - lg * 9;
            const float* Ab = Am + lg * 4 * 44;
            const float* Gb = Gs + rg * 4;
#pragma unroll
            for (int rp4 = 0; rp4 < 9; rp4++) {
                float4 a0 = *(const float4*)(Ab + rp4 * 4);
                float4 a1 = *(const float4*)(Ab + 44 + rp4 * 4);
                float4 a2 = *(const float4*)(Ab + 88 + rp4 * 4);
                float4 a3 = *(const float4*)(Ab + 132 + rp4 * 4);
                if (rp4 == rg) { st0 = a0; st1 = a1; st2 = a2; st3 = a3; }
                float4 g0 = *(const float4*)(Gb + (rp4 * 4 + 0) * 36);
                float4 g1 = *(const float4*)(Gb + (rp4 * 4 + 1) * 36);
                float4 g2 = *(const float4*)(Gb + (rp4 * 4 + 2) * 36);
                float4 g3 = *(const float4*)(Gb + (rp4 * 4 + 3) * 36);
#define ACC4(ACC, AV)                                                          \
                ACC.x = fmaf(AV.x, g0.x, ACC.x); ACC.y = fmaf(AV.x, g0.y, ACC.y); \
                ACC.z = fmaf(AV.x, g0.z, ACC.z); ACC.w = fmaf(AV.x, g0.w, ACC.w); \
                ACC.x = fmaf(AV.y, g1.x, ACC.x); ACC.y = fmaf(AV.y, g1.y, ACC.y); \
                ACC.z = fmaf(AV.y, g1.z, ACC.z); ACC.w = fmaf(AV.y, g1.w, ACC.w); \
                ACC.x = fmaf(AV.z, g2.x, ACC.x); ACC.y = fmaf(AV.z, g2.y, ACC.y); \
                ACC.z = fmaf(AV.z, g2.z, ACC.z); ACC.w = fmaf(AV.z, g2.w, ACC.w); \
                ACC.x = fmaf(AV.w, g3.x, ACC.x); ACC.y = fmaf(AV.w, g3.y, ACC.y); \
                ACC.z = fmaf(AV.w, g3.z, ACC.z); ACC.w = fmaf(AV.w, g3.w, ACC.w);
                ACC4(acc0, a0) ACC4(acc1, a1) ACC4(acc2, a2) ACC4(acc3, a3)
            }
            int l = lg * 4;
            w2p1[(l + 0) * 9 + rg] = acc0.x * st0.x + acc0.y * st0.y + acc0.z * st0.z + acc0.w * st0.w;
            w2p1[(l + 1) * 9 + rg] = acc1.x * st1.x + acc1.y * st1.y + acc1.z * st1.z + acc1.w * st1.w;
            w2p1[(l + 2) * 9 + rg] = acc2.x * st2.x + acc2.y * st2.y + acc2.z * st2.z + acc2.w * st2.w;
            w2p1[(l + 3) * 9 + rg] = acc3.x * st3.x + acc3.y * st3.y + acc3.z * st3.z + acc3.w * st3.w;
        } else {
            int t2 = task - 90;
            int rg = t2 / 10, lg = t2 - rg * 10;
            const float* Cb = Cm + rg * 4 * 44;
            const float* Hb = Hs + lg * 4;
#pragma unroll
            for (int lp4 = 0; lp4 < 10; lp4++) {
                float4 a0 = *(const float4*)(Cb + lp4 * 4);
                float4 a1 = *(const float4*)(Cb + 44 + lp4 * 4);
                float4 a2 = *(const float4*)(Cb + 88 + lp4 * 4);
                float4 a3 = *(const float4*)(Cb + 132 + lp4 * 4);
                if (lp4 == lg) { st0 = a0; st1 = a1; st2 = a2; st3 = a3; }
                float4 g0 = *(const float4*)(Hb + (lp4 * 4 + 0) * 40);
                float4 g1 = *(const float4*)(Hb + (lp4 * 4 + 1) * 40);
                float4 g2 = *(const float4*)(Hb + (lp4 * 4 + 2) * 40);
                float4 g3 = *(const float4*)(Hb + (lp4 * 4 + 3) * 40);
                ACC4(acc0, a0) ACC4(acc1, a1) ACC4(acc2, a2) ACC4(acc3, a3)
#undef ACC4
            }
            int r = rg * 4;
            w2p2[(r + 0) * 10 + lg] = acc0.x * st0.x + acc0.y * st0.y + acc0.z * st0.z + acc0.w * st0.w;
            w2p2[(r + 1) * 10 + lg] = acc1.x * st1.x + acc1.y * st1.y + acc1.z * st1.z + acc1.w * st1.w;
            w2p2[(r + 2) * 10 + lg] = acc2.x * st2.x + acc2.y * st2.y + acc2.z * st2.z + acc2.w * st2.w;
            w2p2[(r + 3) * 10 + lg] = acc3.x * st3.x + acc3.y * st3.y + acc3.z * st3.z + acc3.w * st3.w;
        }
    }
    __syncthreads();

    if (tid < NL) {                          // t2i: word l
        int l = tid; float w12 = 0.f, w2 = 0.f;
#pragma unroll
        for (int r = 0; r < NR; r++) w12 = fmaf(Am[l * 44 + r], Pb[r], w12);
#pragma unroll
        for (int k = 0; k < 9; k++) w2 += w2p1[l * 9 + k];
        float den = fmaxf(g_w1t[i] * sqrtf(fmaxf(w2, 0.f)), EPSF);
        s1s[l] = __fdividef(w12, den);
    } else if (tid >= 64 && tid < 64 + NR) { // i2t: region r
        int r = tid - 64; float w12 = 0.f, w2 = 0.f;
#pragma unroll
        for (int l = 0; l < NL; l++) w12 = fmaf(Cm[r * 44 + l], Qi[l], w12);
#pragma unroll
        for (int k = 0; k < 10; k++) w2 += w2p2[r * 10 + k];
        float den = fmaxf(g_w1i[b] * sqrtf(fmaxf(w2, 0.f)), EPSF);
        s2s[r] = __fdividef(w12, den);
    }
    __syncthreads();

    if (tid == 0) {
        float m1 = 0.f, m2 = 0.f;
#pragma unroll
        for (int l = 0; l < NL; l++) m1 += s1s[l];
#pragma unroll
        for (int r = 0; r < NR; r++) m2 += s2s[r];
        out[(size_t)b * NB + i] = g_base[b * NB + i] + m1 * (1.f / NL) + m2 * (1.f / NR);
    }
}

// ============================ launch ============================
extern "C" void kernel_launch(void* const* d_in, const int* in_sizes, int n_in,
                              void* d_out, int out_size) {
    (void)in_sizes; (void)n_in; (void)out_size;
    const float* pool_img = (const float*)d_in[0];
    const float* img_emb  = (const float*)d_in[1];
    const float* pool_txt = (const float*)d_in[2];
    const float* cap_emb  = (const float*)d_in[3];
    float* out = (float*)d_out;

    cudaFuncSetAttribute((const void*)gram_kernel,
                         cudaFuncAttributeMaxDynamicSharedMemorySize, NL * ND * 4);
    cudaFuncSetAttribute((const void*)s_gemm,
                         cudaFuncAttributeMaxDynamicSharedMemorySize, GEMM_SMEM);
    cudaFuncSetAttribute((const void*)pair_epilogue,
                         cudaFuncAttributeMaxDynamicSharedMemorySize, EPI_SMEM);

    float* dS = nullptr;
    cudaGetSymbolAddress((void**)&dS, g_S);
    __nv_bfloat16* dAh = nullptr; cudaGetSymbolAddress((void**)&dAh, g_Ah);
    __nv_bfloat16* dBh = nullptr; cudaGetSymbolAddress((void**)&dBh, g_Bh);

    // order: s_gemm stays at launch index 3 (profiled slot)
    cvt_kernel<<<9984, 256>>>(img_emb, pool_img, cap_emb, pool_txt);
    gram_kernel<<<NB, 256, NR * ND * 4>>>(img_emb, NR, 0);
    gram_kernel<<<NB, 256, NL * ND * 4>>>(cap_emb, NL, 1);
    s_gemm<<<dim3(41, 74), 256, GEMM_SMEM>>>(dAh, dBh, dS);
    norm_kernel<<<64, 256>>>(pool_img, pool_txt);
    sgemm_tn<<<dim3(NB / 64, NB / 64), 256>>>(pool_img, pool_txt, NB, NB, ND);
    pair_epilogue<<<dim3(NB, NB), 128, EPI_SMEM>>>(dS, out);
}